// round 16
// baseline (speedup 1.0000x reference)
#include <cuda_runtime.h>
#include <cuda_fp16.h>
#include <cuda_bf16.h>
#include <cstdint>

#define SEQ 4096
#define DIM 1024
#define NCOMB 3072  // Q|K|V combined N

// ===========================================================================
// Scratch (allocation-free rule: device globals)
// fp16 comps TILED+SWIZZLED: tile (rb=r/128, kc=k/64) is 16KB contiguous;
// element (r%128,k%64) at byte swz128((r%128)*128+(k%64)*2).
// int8 Q/K TILED+SWIZZLED: tile (rb=r/128, kc=k/128) is 16KB; element at
// byte swz128((r%128)*128+(k%128)). Quant scale 1/0.75 (dequant 0.5625 per
// product).
// ===========================================================================
__device__ float g_QKV[(size_t)SEQ * NCOMB];             // fp32 [Q|K|V]
__device__ __nv_bfloat16 g_S[(size_t)SEQ * SEQ];         // approx scores (bf16, raw)
__device__ __align__(256) __half g_Xc[2][SEQ * DIM];     // x comps, tiled
__device__ __align__(256) __half g_Wc[2][NCOMB * DIM];   // W^T comps, tiled
__device__ __align__(256) int8_t g_Q8[(size_t)SEQ * DIM];
__device__ __align__(256) int8_t g_K8[(size_t)SEQ * DIM];

__device__ __forceinline__ uint32_t smem_u32(const void* p) {
    uint32_t a;
    asm("{ .reg .u64 t; cvta.to.shared.u64 t, %1; cvt.u32.u64 %0, t; }" : "=r"(a) : "l"(p));
    return a;
}
__device__ __forceinline__ uint32_t swz128(uint32_t x) { return x ^ ((x >> 3) & 0x70); }

__device__ __forceinline__ void cpa16(uint32_t dst, const void* src) {
    asm volatile("cp.async.cg.shared.global [%0], [%1], 16;" :: "r"(dst), "l"(src));
}
__device__ __forceinline__ void cp_commit() { asm volatile("cp.async.commit_group;"); }
template <int N>
__device__ __forceinline__ void cp_wait() { asm volatile("cp.async.wait_group %0;" :: "n"(N)); }

__device__ __forceinline__ void ldsm4(uint32_t& r0, uint32_t& r1, uint32_t& r2, uint32_t& r3,
                                      uint32_t addr) {
    asm volatile("ldmatrix.sync.aligned.m8n8.x4.shared.b16 {%0,%1,%2,%3}, [%4];"
                 : "=r"(r0), "=r"(r1), "=r"(r2), "=r"(r3) : "r"(addr));
}
__device__ __forceinline__ void mma16816(float& d0, float& d1, float& d2, float& d3,
                                         uint32_t a0, uint32_t a1, uint32_t a2, uint32_t a3,
                                         uint32_t b0, uint32_t b1) {
    asm volatile(
        "mma.sync.aligned.m16n8k16.row.col.f32.f16.f16.f32 "
        "{%0,%1,%2,%3},{%4,%5,%6,%7},{%8,%9},{%0,%1,%2,%3};"
        : "+f"(d0), "+f"(d1), "+f"(d2), "+f"(d3)
        : "r"(a0), "r"(a1), "r"(a2), "r"(a3), "r"(b0), "r"(b1));
}
// int8 MMA, s32 accum (2x fp16 rate on Ampere-class tensor cores)
__device__ __forceinline__ void mma16832s8(int& d0, int& d1, int& d2, int& d3,
                                           uint32_t a0, uint32_t a1, uint32_t a2, uint32_t a3,
                                           uint32_t b0, uint32_t b1) {
    asm volatile(
        "mma.sync.aligned.m16n8k32.row.col.s32.s8.s8.s32 "
        "{%0,%1,%2,%3},{%4,%5,%6,%7},{%8,%9},{%0,%1,%2,%3};"
        : "+r"(d0), "+r"(d1), "+r"(d2), "+r"(d3)
        : "r"(a0), "r"(a1), "r"(a2), "r"(a3), "r"(b0), "r"(b1));
}
__device__ __forceinline__ uint32_t pack_h2(float a, float b) {
    __half2 h = __floats2half2_rn(a, b);
    return *reinterpret_cast<uint32_t*>(&h);
}
__device__ __forceinline__ uint32_t pack_bf2(float a, float b) {
    __nv_bfloat162 h = __floats2bfloat162_rn(a, b);
    return *reinterpret_cast<uint32_t*>(&h);
}

// ===========================================================================
// Splits: fp32 -> 2 exact fp16 comps, tiled+swizzled layout.
// ===========================================================================
__global__ __launch_bounds__(256)
void split_direct2(const float* __restrict__ in, __half* __restrict__ o0,
                   __half* __restrict__ o1) {
    const int kt = DIM >> 6;
    const size_t tot8 = ((size_t)SEQ * DIM) >> 3;
    for (size_t t = (size_t)blockIdx.x * blockDim.x + threadIdx.x; t < tot8;
         t += (size_t)gridDim.x * blockDim.x) {
        const size_t idx = t << 3;
        const int r = (int)(idx >> 10);
        const int k = (int)(idx & (DIM - 1));
        float x[8];
        *reinterpret_cast<float4*>(&x[0]) = *reinterpret_cast<const float4*>(in + idx);
        *reinterpret_cast<float4*>(&x[4]) = *reinterpret_cast<const float4*>(in + idx + 4);
        uint4 H, M;
        uint32_t* hp = reinterpret_cast<uint32_t*>(&H);
        uint32_t* mp = reinterpret_cast<uint32_t*>(&M);
#pragma unroll
        for (int j = 0; j < 4; j++) {
            float x0 = x[2 * j], x1 = x[2 * j + 1];
            __half h0 = __float2half_rn(x0), h1 = __float2half_rn(x1);
            float m0 = x0 - __half2float(h0), m1 = x1 - __half2float(h1);
            hp[j] = pack_h2(__half2float(h0), __half2float(h1));
            mp[j] = pack_h2(m0, m1);
        }
        const size_t tbB = ((size_t)(r >> 7) * kt + (k >> 6)) * 16384;
        const uint32_t off = swz128(((r & 127) << 7) + ((k & 63) << 1));
        *reinterpret_cast<uint4*>(reinterpret_cast<char*>(o0) + tbB + off) = H;
        *reinterpret_cast<uint4*>(reinterpret_cast<char*>(o1) + tbB + off) = M;
    }
}

// Transpose-split all three weight matrices in one launch (blockIdx.y selects).
__global__ __launch_bounds__(256)
void split_trans_w(const float* __restrict__ wq, const float* __restrict__ wk,
                   const float* __restrict__ wv, __half* __restrict__ o0base,
                   __half* __restrict__ o1base) {
    const int which = blockIdx.y;
    const float* in = (which == 0) ? wq : (which == 1) ? wk : wv;
    __half* o0 = o0base + (size_t)which * DIM * DIM;
    __half* o1 = o1base + (size_t)which * DIM * DIM;
    const int kt = DIM >> 6;
    const size_t tot = ((size_t)DIM >> 3) * DIM;
    for (size_t t = (size_t)blockIdx.x * blockDim.x + threadIdx.x; t < tot;
         t += (size_t)gridDim.x * blockDim.x) {
        const int i = (int)(t & (DIM - 1));
        const int k = (int)(t / DIM) << 3;
        uint4 H, M;
        uint32_t* hp = reinterpret_cast<uint32_t*>(&H);
        uint32_t* mp = reinterpret_cast<uint32_t*>(&M);
#pragma unroll
        for (int j = 0; j < 4; j++) {
            float x0 = in[(size_t)(k + 2 * j) * DIM + i];
            float x1 = in[(size_t)(k + 2 * j + 1) * DIM + i];
            __half h0 = __float2half_rn(x0), h1 = __float2half_rn(x1);
            float m0 = x0 - __half2float(h0), m1 = x1 - __half2float(h1);
            hp[j] = pack_h2(__half2float(h0), __half2float(h1));
            mp[j] = pack_h2(m0, m1);
        }
        const size_t tbB = ((size_t)(i >> 7) * kt + (k >> 6)) * 16384;
        const uint32_t off = swz128(((i & 127) << 7) + ((k & 63) << 1));
        *reinterpret_cast<uint4*>(reinterpret_cast<char*>(o0) + tbB + off) = H;
        *reinterpret_cast<uint4*>(reinterpret_cast<char*>(o1) + tbB + off) = M;
    }
}

// ===========================================================================
// PROJ GEMM: CTA 128x256, 512 threads, 16 warps (4m x 4n), warp m32n64,
// shared fragments. Q/K blocks (blockIdx.x < 8): 3 products + int8 quantized
// output (Q8/K8, scale 1/0.75). V blocks: 2 products, fp32 only.
// 2-stage, 96KB/stage.
// ===========================================================================
__global__ __launch_bounds__(512, 1)
void proj_hmma(const __half* __restrict__ A0p, const __half* __restrict__ A1p,
               const __half* __restrict__ B0p, const __half* __restrict__ B1p,
               float* __restrict__ C, int8_t* __restrict__ Q8, int8_t* __restrict__ K8,
               int Cstride, int nch, int ktA, int ktB) {
    constexpr uint32_t STAGE_B = 6 * 16384u;

    extern __shared__ char smem[];
    const uint32_t sb = (smem_u32(smem) + 1023) & ~1023u;
    const int tid = threadIdx.x;
    const int wid = tid >> 5, lane = tid & 31;
    const int wm = wid >> 2, wn = wid & 3;  // 4m x 4n, warp m32n64
    const bool full3 = (blockIdx.x < 8);    // Q,K blocks: 3 products; V: 2

    const char* srcA0 = reinterpret_cast<const char*>(A0p) + (size_t)blockIdx.y * ktA * 16384;
    const char* srcA1 = reinterpret_cast<const char*>(A1p) + (size_t)blockIdx.y * ktA * 16384;
    const char* srcB0a = reinterpret_cast<const char*>(B0p) + (size_t)(2 * blockIdx.x) * ktB * 16384;
    const char* srcB0b = reinterpret_cast<const char*>(B0p) + (size_t)(2 * blockIdx.x + 1) * ktB * 16384;
    const char* srcB1a = reinterpret_cast<const char*>(B1p) + (size_t)(2 * blockIdx.x) * ktB * 16384;
    const char* srcB1b = reinterpret_cast<const char*>(B1p) + (size_t)(2 * blockIdx.x + 1) * ktB * 16384;

    auto copy_stage = [&](int s, int it) {
        const uint32_t dst = sb + (uint32_t)s * STAGE_B;
        const uint32_t lo = tid * 16;
        const size_t go = (size_t)it * 16384 + lo;
#pragma unroll
        for (int i = 0; i < 2; i++) {
            cpa16(dst + lo + i * 8192, srcA0 + go + i * 8192);
            if (full3) cpa16(dst + 16384u + lo + i * 8192, srcA1 + go + i * 8192);
            cpa16(dst + 32768u + lo + i * 8192, srcB0a + go + i * 8192);
            cpa16(dst + 49152u + lo + i * 8192, srcB0b + go + i * 8192);
            cpa16(dst + 65536u + lo + i * 8192, srcB1a + go + i * 8192);
            cpa16(dst + 81920u + lo + i * 8192, srcB1b + go + i * 8192);
        }
    };

    copy_stage(0, 0);
    cp_commit();

    float acc[2][8][4];
#pragma unroll
    for (int a = 0; a < 2; a++)
#pragma unroll
        for (int b = 0; b < 8; b++)
#pragma unroll
            for (int c = 0; c < 4; c++) acc[a][b][c] = 0.0f;

    const int rowA = wm * 32 + (lane & 15);
    const int kadjA = (lane >> 4) * 8;
    const int rowB = (wn & 1) * 64 + (lane & 7) + ((lane >> 4) << 3);
    const int kadjB = ((lane >> 3) & 1) * 8;
    const uint32_t bTileOff = (uint32_t)(wn >> 1) * 16384u;

    for (int it = 0; it < nch; it++) {
        const int s = it & 1;
        const int nxt = it + 1;
        if (nxt < nch) copy_stage(nxt & 1, nxt);
        cp_commit();
        cp_wait<1>();
        __syncthreads();
        const uint32_t st = sb + (uint32_t)s * STAGE_B;
        const uint32_t B0b = st + 32768u + bTileOff;
        const uint32_t B1b = st + 65536u + bTileOff;
#pragma unroll
        for (int ks = 0; ks < 4; ks++) {
            const int k0 = ks * 16;
            uint32_t b0[8][2], b1[8][2];
#pragma unroll
            for (int nh = 0; nh < 4; nh++) {
                uint32_t rel = (uint32_t)((rowB + nh * 16) << 7) + ((k0 + kadjB) << 1);
                uint32_t r0, r1, r2, r3;
                ldsm4(r0, r1, r2, r3, B0b + swz128(rel));
                b0[nh * 2][0] = r0; b0[nh * 2][1] = r1;
                b0[nh * 2 + 1][0] = r2; b0[nh * 2 + 1][1] = r3;
                ldsm4(r0, r1, r2, r3, B1b + swz128(rel));
                b1[nh * 2][0] = r0; b1[nh * 2][1] = r1;
                b1[nh * 2 + 1][0] = r2; b1[nh * 2 + 1][1] = r3;
            }
#pragma unroll
            for (int mi = 0; mi < 2; mi++) {
                uint32_t rel = (uint32_t)((rowA + mi * 16) << 7) + ((k0 + kadjA) << 1);
                uint32_t a00, a01, a02, a03, a10, a11, a12, a13;
                ldsm4(a00, a01, a02, a03, st + swz128(rel));
                if (full3) ldsm4(a10, a11, a12, a13, st + 16384u + swz128(rel));
#pragma unroll
                for (int nj = 0; nj < 8; nj++) {
                    mma16816(acc[mi][nj][0], acc[mi][nj][1], acc[mi][nj][2], acc[mi][nj][3],
                             a00, a01, a02, a03, b0[nj][0], b0[nj][1]);
                    mma16816(acc[mi][nj][0], acc[mi][nj][1], acc[mi][nj][2], acc[mi][nj][3],
                             a00, a01, a02, a03, b1[nj][0], b1[nj][1]);
                    if (full3)
                        mma16816(acc[mi][nj][0], acc[mi][nj][1], acc[mi][nj][2], acc[mi][nj][3],
                                 a10, a11, a12, a13, b0[nj][0], b0[nj][1]);
                }
            }
        }
        __syncthreads();
    }

    // epilogue: fp32 C everywhere; int8 quantized Q/K for blockIdx.x < 8
    const int g = lane >> 2, tig = lane & 3;
    const bool isQ = blockIdx.x < 4;
    int8_t* dst8 = isQ ? Q8 : K8;
    const int kb = (isQ ? blockIdx.x : blockIdx.x - 4) * 256;
#pragma unroll
    for (int mi = 0; mi < 2; mi++) {
        const int r0 = blockIdx.y * 128 + wm * 32 + mi * 16 + g;
#pragma unroll
        for (int nj = 0; nj < 8; nj++) {
            const int c = blockIdx.x * 256 + wn * 64 + nj * 8 + 2 * tig;
            *reinterpret_cast<float2*>(&C[(size_t)r0 * Cstride + c]) =
                make_float2(acc[mi][nj][0], acc[mi][nj][1]);
            *reinterpret_cast<float2*>(&C[(size_t)(r0 + 8) * Cstride + c]) =
                make_float2(acc[mi][nj][2], acc[mi][nj][3]);
            if (full3) {
                const int k = kb + wn * 64 + nj * 8 + 2 * tig;
#pragma unroll
                for (int h = 0; h < 2; h++) {
                    const int r = r0 + h * 8;
                    int q0 = __float2int_rn(acc[mi][nj][2 * h] * 1.3333333f);
                    int q1 = __float2int_rn(acc[mi][nj][2 * h + 1] * 1.3333333f);
                    q0 = max(-127, min(127, q0));
                    q1 = max(-127, min(127, q1));
                    const uint16_t pk =
                        (uint16_t)((uint8_t)(int8_t)q0) | ((uint16_t)((uint8_t)(int8_t)q1) << 8);
                    const size_t tb = ((size_t)(r >> 7) * 8 + (k >> 7)) * 16384;
                    const uint32_t off = swz128(((r & 127) << 7) + (k & 127));
                    *reinterpret_cast<uint16_t*>(
                        reinterpret_cast<char*>(dst8) + tb + off) = pk;
                }
            }
        }
    }
}

// ===========================================================================
// SCORES GEMM, INT8: CTA 128x128, 256 threads, 8 warps (2m x 4n), warp
// m64n32, s32 accum. S_approx = (Q8.K8)*0.5625 stored bf16 (raw scale).
// 2-stage 32KB/stage -> 2 CTAs/SM, 4 warps/SMSP. MMA:LDS ~ 128:96 cyc.
// ===========================================================================
__global__ __launch_bounds__(256, 2)
void score_i8(const int8_t* __restrict__ Q8p, const int8_t* __restrict__ K8p,
              __nv_bfloat16* __restrict__ Cb, int Cstride, int nch) {
    constexpr uint32_t STAGE_B = 2 * 16384u;

    extern __shared__ char smem[];
    const uint32_t sb = (smem_u32(smem) + 1023) & ~1023u;
    const int tid = threadIdx.x;
    const int wid = tid >> 5, lane = tid & 31;
    const int wm = wid >> 2, wn = wid & 3;  // 2m x 4n, warp m64n32

    const char* srcA = reinterpret_cast<const char*>(Q8p) + (size_t)blockIdx.y * nch * 16384;
    const char* srcB = reinterpret_cast<const char*>(K8p) + (size_t)blockIdx.x * nch * 16384;

    auto copy_stage = [&](int s, int it) {
        const uint32_t dst = sb + (uint32_t)s * STAGE_B;
        const uint32_t lo = tid * 16;
        const size_t go = (size_t)it * 16384 + lo;
#pragma unroll
        for (int i = 0; i < 4; i++) {
            cpa16(dst + lo + i * 4096, srcA + go + i * 4096);
            cpa16(dst + 16384u + lo + i * 4096, srcB + go + i * 4096);
        }
    };

    copy_stage(0, 0);
    cp_commit();

    int acc[4][4][4];
#pragma unroll
    for (int a = 0; a < 4; a++)
#pragma unroll
        for (int b = 0; b < 4; b++)
#pragma unroll
            for (int c = 0; c < 4; c++) acc[a][b][c] = 0;

    // int8 tile: 128 rows x 128 bytes, swz128 over 16B units.
    const int rowA = wm * 64 + (lane & 15);
    const int kadjA = (lane >> 4) * 16;  // bytes
    const int rowB = wn * 32 + (lane & 7) + ((lane >> 4) << 3);
    const int kadjB = ((lane >> 3) & 1) * 16;  // bytes

    for (int it = 0; it < nch; it++) {
        const int s = it & 1;
        const int nxt = it + 1;
        if (nxt < nch) copy_stage(nxt & 1, nxt);
        cp_commit();
        cp_wait<1>();
        __syncthreads();
        const uint32_t st = sb + (uint32_t)s * STAGE_B;
        const uint32_t Ab = st;
        const uint32_t Bb = st + 16384u;
#pragma unroll
        for (int ks = 0; ks < 4; ks++) {
            const int k0 = ks * 32;  // bytes (k32 per mma)
            uint32_t b[4][2];
#pragma unroll
            for (int nh = 0; nh < 2; nh++) {
                uint32_t rel = (uint32_t)((rowB + nh * 16) << 7) + k0 + kadjB;
                uint32_t r0, r1, r2, r3;
                ldsm4(r0, r1, r2, r3, Bb + swz128(rel));
                b[nh * 2][0] = r0; b[nh * 2][1] = r1;
                b[nh * 2 + 1][0] = r2; b[nh * 2 + 1][1] = r3;
            }
#pragma unroll
            for (int mi = 0; mi < 4; mi++) {
                uint32_t a0, a1, a2, a3;
                uint32_t rel = (uint32_t)((rowA + mi * 16) << 7) + k0 + kadjA;
                ldsm4(a0, a1, a2, a3, Ab + swz128(rel));
#pragma unroll
                for (int nj = 0; nj < 4; nj++)
                    mma16832s8(acc[mi][nj][0], acc[mi][nj][1], acc[mi][nj][2], acc[mi][nj][3],
                               a0, a1, a2, a3, b[nj][0], b[nj][1]);
            }
        }
        __syncthreads();
    }

    const int g = lane >> 2, tig = lane & 3;
    const float DQ = 0.5625f;  // 0.75^2
#pragma unroll
    for (int mi = 0; mi < 4; mi++) {
        const int r0 = blockIdx.y * 128 + wm * 64 + mi * 16 + g;
#pragma unroll
        for (int nj = 0; nj < 4; nj++) {
            const int c = blockIdx.x * 128 + wn * 32 + nj * 8 + 2 * tig;
            *reinterpret_cast<uint32_t*>(&Cb[(size_t)r0 * Cstride + c]) =
                pack_bf2((float)acc[mi][nj][0] * DQ, (float)acc[mi][nj][1] * DQ);
            *reinterpret_cast<uint32_t*>(&Cb[(size_t)(r0 + 8) * Cstride + c]) =
                pack_bf2((float)acc[mi][nj][2] * DQ, (float)acc[mi][nj][3] * DQ);
        }
    }
}

// ===========================================================================
// Fused: candidate select on bf16 approx scores + exact fp32 re-score +
// softmax weights + sparse P@V gather. One block per row.
// Margin 4500 = 737 (1e-10 mass) + 2*(int8 quant ~1200 incl clamp tails +
// bf16 store ~130) + slack. Candidates re-scored exactly.
// ===========================================================================
__global__ __launch_bounds__(256)
void attn_refine(const __nv_bfloat16* __restrict__ St, const float* __restrict__ QKV,
                 float* __restrict__ out) {
    __shared__ float red[256];
    __shared__ int sc[256];
    __shared__ int cand[SEQ];
    __shared__ float sE[SEQ];
    __shared__ float Qs[DIM];
    const int row = blockIdx.x;
    const int tid = threadIdx.x;
    const int wid = tid >> 5, lane = tid & 31;

    const uint4* p4 = reinterpret_cast<const uint4*>(St + (size_t)row * SEQ);
    uint4 u[2];
    u[0] = p4[tid];
    u[1] = p4[tid + 256];
    float e[16];
#pragma unroll
    for (int w = 0; w < 2; w++)
#pragma unroll
        for (int j = 0; j < 4; j++) {
            const __nv_bfloat162 h = reinterpret_cast<const __nv_bfloat162*>(&u[w])[j];
            const float2 f = __bfloat1622float2(h);
            e[w * 8 + 2 * j] = f.x;
            e[w * 8 + 2 * j + 1] = f.y;
        }
    float vmax = -3.0e38f;
#pragma unroll
    for (int i = 0; i < 16; i++) vmax = fmaxf(vmax, e[i]);
    red[tid] = vmax;
    Qs[tid] = QKV[(size_t)row * NCOMB + tid];
    Qs[tid + 256] = QKV[(size_t)row * NCOMB + tid + 256];
    Qs[tid + 512] = QKV[(size_t)row * NCOMB + tid + 512];
    Qs[tid + 768] = QKV[(size_t)row * NCOMB + tid + 768];
    __syncthreads();
#pragma unroll
    for (int s = 128; s > 0; s >>= 1) {
        if (tid < s) red[tid] = fmaxf(red[tid], red[tid + s]);
        __syncthreads();
    }
    const float T = red[0] - 4500.0f;
    __syncthreads();

    int cnt = 0;
#pragma unroll
    for (int i = 0; i < 16; i++)
        if (e[i] >= T) cnt++;
    sc[tid] = cnt;
    __syncthreads();
    for (int d = 1; d < 256; d <<= 1) {
        int val = (tid >= d) ? sc[tid - d] : 0;
        __syncthreads();
        sc[tid] += val;
        __syncthreads();
    }
    int base = sc[tid] - cnt;
    const int total = sc[255];
#pragma unroll
    for (int w = 0; w < 2; w++)
#pragma unroll
        for (int j = 0; j < 8; j++) {
            const int i = w * 8 + j;
            if (e[i] >= T) cand[base++] = w * 2048 + tid * 8 + j;
        }
    __syncthreads();

    const float4* Qs4 = reinterpret_cast<const float4*>(Qs);
    for (int c = wid; c < total; c += 8) {
        const int j = cand[c];
        const float4* Kr = reinterpret_cast<const float4*>(QKV + (size_t)j * NCOMB + DIM);
        float s = 0.0f;
#pragma unroll
        for (int t = 0; t < 8; t++) {
            const float4 kv = Kr[lane + 32 * t];
            const float4 qv = Qs4[lane + 32 * t];
            s += qv.x * kv.x + qv.y * kv.y + qv.z * kv.z + qv.w * kv.w;
        }
#pragma unroll
        for (int o = 16; o > 0; o >>= 1) s += __shfl_xor_sync(0xFFFFFFFFu, s, o);
        if (lane == 0) sE[c] = s;
    }
    __syncthreads();

    float M = -3.0e38f;
    for (int c = 0; c < total; c++) M = fmaxf(M, sE[c]);
    float sum = 0.0f;
    for (int c = 0; c < total; c++) sum += expf((sE[c] - M) * 0.03125f);
    const float inv = 1.0f / sum;

    float4 acc = make_float4(0.f, 0.f, 0.f, 0.f);
    for (int c = 0; c < total; c++) {
        const float w = expf((sE[c] - M) * 0.03125f);
        const float4 vv = *reinterpret_cast<const float4*>(
            QKV + (size_t)cand[c] * NCOMB + 2 * DIM + 4 * tid);
        acc.x += w * vv.x; acc.y += w * vv.y; acc.z += w * vv.z; acc.w += w * vv.w;
    }
    acc.x *= inv; acc.y *= inv; acc.z *= inv; acc.w *= inv;
    *reinterpret_cast<float4*>(out + (size_t)row * DIM + 4 * tid) = acc;
}

// ===========================================================================
extern "C" void kernel_launch(void* const* d_in, const int* in_sizes, int n_in,
                              void* d_out, int out_size) {
    const float* x  = (const float*)d_in[0];
    const float* wq = (const float*)d_in[1];
    const float* wk = (const float*)d_in[2];
    const float* wv = (const float*)d_in[3];
    float* out = (float*)d_out;

    float* QKV;
    __nv_bfloat16* S;
    __half *Xc, *Wc;
    int8_t *Q8, *K8;
    cudaGetSymbolAddress((void**)&QKV, g_QKV);
    cudaGetSymbolAddress((void**)&S, g_S);
    cudaGetSymbolAddress((void**)&Xc, g_Xc);
    cudaGetSymbolAddress((void**)&Wc, g_Wc);
    cudaGetSymbolAddress((void**)&Q8, g_Q8);
    cudaGetSymbolAddress((void**)&K8, g_K8);
    const size_t SD = (size_t)SEQ * DIM;
    const size_t WN = (size_t)NCOMB * DIM;

    constexpr int SMEM_PROJ = 2 * 98304 + 1024;   // 2 stages x 6 tiles
    constexpr int SMEM_SCORE = 2 * 32768 + 1024;  // 2 stages x 2 int8 tiles
    cudaFuncSetAttribute(proj_hmma, cudaFuncAttributeMaxDynamicSharedMemorySize, SMEM_PROJ);
    cudaFuncSetAttribute(score_i8, cudaFuncAttributeMaxDynamicSharedMemorySize, SMEM_SCORE);

    // splits
    split_direct2<<<512, 256>>>(x, Xc, Xc + SD);
    split_trans_w<<<dim3(128, 3), 256>>>(wq, wk, wv, Wc, Wc + WN);

    // fused QKV projection -> fp32 QKV + int8 Q8/K8
    proj_hmma<<<dim3(NCOMB / 256, SEQ / 128), 512, SMEM_PROJ>>>(
        Xc, Xc + SD, Wc, Wc + WN, QKV, Q8, K8, NCOMB, DIM / 64, DIM / 64, DIM / 64);

    // approx scores: int8 Q8 @ K8^T (bf16 out, s32 accum)
    score_i8<<<dim3(SEQ / 128, SEQ / 128), 256, SMEM_SCORE>>>(Q8, K8, S, SEQ, DIM / 128);

    // candidate refine + softmax + sparse P@V
    attn_refine<<<SEQ, 256>>>(S, QKV, out);
}

// round 17
// speedup vs baseline: 1.5517x; 1.5517x over previous
#include <cuda_runtime.h>
#include <cuda_fp16.h>
#include <cuda_bf16.h>
#include <cstdint>

#define SEQ 4096
#define DIM 1024
#define NCOMB 3072  // Q|K|V combined N

// ===========================================================================
// Scratch (allocation-free rule: device globals)
// fp16 comps TILED+SWIZZLED: tile (rb=r/128, kc=k/64) is 16KB contiguous;
// element (r%128,k%64) at byte swz128((r%128)*128+(k%64)*2).
// Hc holds SCALED (x0.125) hi comps: stored approx scores are S/64.
// ===========================================================================
__device__ float g_QKV[(size_t)SEQ * NCOMB];                 // fp32 [Q|K|V]
__device__ __nv_bfloat16 g_S[(size_t)SEQ * SEQ];             // approx scores / 64 (bf16)
__device__ __align__(256) __half g_Xc[2][SEQ * DIM];         // x comps, tiled
__device__ __align__(256) __half g_Wc[2][NCOMB * DIM];       // W^T comps, tiled
__device__ __align__(256) __half g_Hc[(size_t)SEQ * NCOMB];  // 0.125*hi comps (Q/K used)

__device__ __forceinline__ uint32_t smem_u32(const void* p) {
    uint32_t a;
    asm("{ .reg .u64 t; cvta.to.shared.u64 t, %1; cvt.u32.u64 %0, t; }" : "=r"(a) : "l"(p));
    return a;
}
__device__ __forceinline__ uint32_t swz128(uint32_t x) { return x ^ ((x >> 3) & 0x70); }

__device__ __forceinline__ void cpa16(uint32_t dst, const void* src) {
    asm volatile("cp.async.cg.shared.global [%0], [%1], 16;" :: "r"(dst), "l"(src));
}
__device__ __forceinline__ void cp_commit() { asm volatile("cp.async.commit_group;"); }
template <int N>
__device__ __forceinline__ void cp_wait() { asm volatile("cp.async.wait_group %0;" :: "n"(N)); }

__device__ __forceinline__ void ldsm4(uint32_t& r0, uint32_t& r1, uint32_t& r2, uint32_t& r3,
                                      uint32_t addr) {
    asm volatile("ldmatrix.sync.aligned.m8n8.x4.shared.b16 {%0,%1,%2,%3}, [%4];"
                 : "=r"(r0), "=r"(r1), "=r"(r2), "=r"(r3) : "r"(addr));
}
__device__ __forceinline__ void mma16816(float& d0, float& d1, float& d2, float& d3,
                                         uint32_t a0, uint32_t a1, uint32_t a2, uint32_t a3,
                                         uint32_t b0, uint32_t b1) {
    asm volatile(
        "mma.sync.aligned.m16n8k16.row.col.f32.f16.f16.f32 "
        "{%0,%1,%2,%3},{%4,%5,%6,%7},{%8,%9},{%0,%1,%2,%3};"
        : "+f"(d0), "+f"(d1), "+f"(d2), "+f"(d3)
        : "r"(a0), "r"(a1), "r"(a2), "r"(a3), "r"(b0), "r"(b1));
}
// fp16-accumulator variant (half the acc registers)
__device__ __forceinline__ void mma16816h(uint32_t& d0, uint32_t& d1,
                                          uint32_t a0, uint32_t a1, uint32_t a2, uint32_t a3,
                                          uint32_t b0, uint32_t b1) {
    asm volatile(
        "mma.sync.aligned.m16n8k16.row.col.f16.f16.f16.f16 "
        "{%0,%1},{%2,%3,%4,%5},{%6,%7},{%0,%1};"
        : "+r"(d0), "+r"(d1)
        : "r"(a0), "r"(a1), "r"(a2), "r"(a3), "r"(b0), "r"(b1));
}
__device__ __forceinline__ uint32_t pack_h2(float a, float b) {
    __half2 h = __floats2half2_rn(a, b);
    return *reinterpret_cast<uint32_t*>(&h);
}
__device__ __forceinline__ uint32_t pack_bf2(float a, float b) {
    __nv_bfloat162 h = __floats2bfloat162_rn(a, b);
    return *reinterpret_cast<uint32_t*>(&h);
}

// ===========================================================================
// Splits: fp32 -> 2 exact fp16 comps, tiled+swizzled layout.
// ===========================================================================
__global__ __launch_bounds__(256)
void split_direct2(const float* __restrict__ in, __half* __restrict__ o0,
                   __half* __restrict__ o1) {
    const int kt = DIM >> 6;
    const size_t tot8 = ((size_t)SEQ * DIM) >> 3;
    for (size_t t = (size_t)blockIdx.x * blockDim.x + threadIdx.x; t < tot8;
         t += (size_t)gridDim.x * blockDim.x) {
        const size_t idx = t << 3;
        const int r = (int)(idx >> 10);
        const int k = (int)(idx & (DIM - 1));
        float x[8];
        *reinterpret_cast<float4*>(&x[0]) = *reinterpret_cast<const float4*>(in + idx);
        *reinterpret_cast<float4*>(&x[4]) = *reinterpret_cast<const float4*>(in + idx + 4);
        uint4 H, M;
        uint32_t* hp = reinterpret_cast<uint32_t*>(&H);
        uint32_t* mp = reinterpret_cast<uint32_t*>(&M);
#pragma unroll
        for (int j = 0; j < 4; j++) {
            float x0 = x[2 * j], x1 = x[2 * j + 1];
            __half h0 = __float2half_rn(x0), h1 = __float2half_rn(x1);
            float m0 = x0 - __half2float(h0), m1 = x1 - __half2float(h1);
            hp[j] = pack_h2(__half2float(h0), __half2float(h1));
            mp[j] = pack_h2(m0, m1);
        }
        const size_t tbB = ((size_t)(r >> 7) * kt + (k >> 6)) * 16384;
        const uint32_t off = swz128(((r & 127) << 7) + ((k & 63) << 1));
        *reinterpret_cast<uint4*>(reinterpret_cast<char*>(o0) + tbB + off) = H;
        *reinterpret_cast<uint4*>(reinterpret_cast<char*>(o1) + tbB + off) = M;
    }
}

// Transpose-split all three weight matrices in one launch (blockIdx.y selects).
__global__ __launch_bounds__(256)
void split_trans_w(const float* __restrict__ wq, const float* __restrict__ wk,
                   const float* __restrict__ wv, __half* __restrict__ o0base,
                   __half* __restrict__ o1base) {
    const int which = blockIdx.y;
    const float* in = (which == 0) ? wq : (which == 1) ? wk : wv;
    __half* o0 = o0base + (size_t)which * DIM * DIM;
    __half* o1 = o1base + (size_t)which * DIM * DIM;
    const int kt = DIM >> 6;
    const size_t tot = ((size_t)DIM >> 3) * DIM;
    for (size_t t = (size_t)blockIdx.x * blockDim.x + threadIdx.x; t < tot;
         t += (size_t)gridDim.x * blockDim.x) {
        const int i = (int)(t & (DIM - 1));
        const int k = (int)(t / DIM) << 3;
        uint4 H, M;
        uint32_t* hp = reinterpret_cast<uint32_t*>(&H);
        uint32_t* mp = reinterpret_cast<uint32_t*>(&M);
#pragma unroll
        for (int j = 0; j < 4; j++) {
            float x0 = in[(size_t)(k + 2 * j) * DIM + i];
            float x1 = in[(size_t)(k + 2 * j + 1) * DIM + i];
            __half h0 = __float2half_rn(x0), h1 = __float2half_rn(x1);
            float m0 = x0 - __half2float(h0), m1 = x1 - __half2float(h1);
            hp[j] = pack_h2(__half2float(h0), __half2float(h1));
            mp[j] = pack_h2(m0, m1);
        }
        const size_t tbB = ((size_t)(i >> 7) * kt + (k >> 6)) * 16384;
        const uint32_t off = swz128(((i & 127) << 7) + ((k & 63) << 1));
        *reinterpret_cast<uint4*>(reinterpret_cast<char*>(o0) + tbB + off) = H;
        *reinterpret_cast<uint4*>(reinterpret_cast<char*>(o1) + tbB + off) = M;
    }
}

// ===========================================================================
// PROJ GEMM: CTA 128x256, 512 threads, 16 warps (4m x 4n), warp m32n64,
// shared fragments. Q/K blocks (blockIdx.x < 8): 3 products {hh,hm,mh} +
// scaled fp16 hi comp out. V blocks: 1 product {hh} only (errors pass
// linearly through softmax-weighted sum; ~1e-4 rel). 2-stage, 96KB/stage.
// ===========================================================================
__global__ __launch_bounds__(512, 1)
void proj_hmma(const __half* __restrict__ A0p, const __half* __restrict__ A1p,
               const __half* __restrict__ B0p, const __half* __restrict__ B1p,
               float* __restrict__ C, __half* __restrict__ Ohi,
               int Cstride, int nch, int ktA, int ktB, int ktO) {
    constexpr uint32_t STAGE_B = 6 * 16384u;

    extern __shared__ char smem[];
    const uint32_t sb = (smem_u32(smem) + 1023) & ~1023u;
    const int tid = threadIdx.x;
    const int wid = tid >> 5, lane = tid & 31;
    const int wm = wid >> 2, wn = wid & 3;  // 4m x 4n, warp m32n64
    const bool full3 = (blockIdx.x < 8);    // Q,K blocks: 3 products; V: 1

    const char* srcA0 = reinterpret_cast<const char*>(A0p) + (size_t)blockIdx.y * ktA * 16384;
    const char* srcA1 = reinterpret_cast<const char*>(A1p) + (size_t)blockIdx.y * ktA * 16384;
    const char* srcB0a = reinterpret_cast<const char*>(B0p) + (size_t)(2 * blockIdx.x) * ktB * 16384;
    const char* srcB0b = reinterpret_cast<const char*>(B0p) + (size_t)(2 * blockIdx.x + 1) * ktB * 16384;
    const char* srcB1a = reinterpret_cast<const char*>(B1p) + (size_t)(2 * blockIdx.x) * ktB * 16384;
    const char* srcB1b = reinterpret_cast<const char*>(B1p) + (size_t)(2 * blockIdx.x + 1) * ktB * 16384;

    auto copy_stage = [&](int s, int it) {
        const uint32_t dst = sb + (uint32_t)s * STAGE_B;
        const uint32_t lo = tid * 16;  // 512 thr x 16B = 8KB sweep
        const size_t go = (size_t)it * 16384 + lo;
#pragma unroll
        for (int i = 0; i < 2; i++) {
            cpa16(dst + lo + i * 8192, srcA0 + go + i * 8192);
            cpa16(dst + 32768u + lo + i * 8192, srcB0a + go + i * 8192);
            cpa16(dst + 49152u + lo + i * 8192, srcB0b + go + i * 8192);
            if (full3) {
                cpa16(dst + 16384u + lo + i * 8192, srcA1 + go + i * 8192);
                cpa16(dst + 65536u + lo + i * 8192, srcB1a + go + i * 8192);
                cpa16(dst + 81920u + lo + i * 8192, srcB1b + go + i * 8192);
            }
        }
    };

    copy_stage(0, 0);
    cp_commit();

    float acc[2][8][4];
#pragma unroll
    for (int a = 0; a < 2; a++)
#pragma unroll
        for (int b = 0; b < 8; b++)
#pragma unroll
            for (int c = 0; c < 4; c++) acc[a][b][c] = 0.0f;

    const int rowA = wm * 32 + (lane & 15);
    const int kadjA = (lane >> 4) * 8;
    const int rowB = (wn & 1) * 64 + (lane & 7) + ((lane >> 4) << 3);
    const int kadjB = ((lane >> 3) & 1) * 8;
    const uint32_t bTileOff = (uint32_t)(wn >> 1) * 16384u;

    for (int it = 0; it < nch; it++) {
        const int s = it & 1;
        const int nxt = it + 1;
        if (nxt < nch) copy_stage(nxt & 1, nxt);
        cp_commit();
        cp_wait<1>();
        __syncthreads();
        const uint32_t st = sb + (uint32_t)s * STAGE_B;
        const uint32_t B0b = st + 32768u + bTileOff;
        const uint32_t B1b = st + 65536u + bTileOff;
#pragma unroll
        for (int ks = 0; ks < 4; ks++) {
            const int k0 = ks * 16;
            uint32_t b0[8][2], b1[8][2];
#pragma unroll
            for (int nh = 0; nh < 4; nh++) {
                uint32_t rel = (uint32_t)((rowB + nh * 16) << 7) + ((k0 + kadjB) << 1);
                uint32_t r0, r1, r2, r3;
                ldsm4(r0, r1, r2, r3, B0b + swz128(rel));
                b0[nh * 2][0] = r0; b0[nh * 2][1] = r1;
                b0[nh * 2 + 1][0] = r2; b0[nh * 2 + 1][1] = r3;
                if (full3) {
                    ldsm4(r0, r1, r2, r3, B1b + swz128(rel));
                    b1[nh * 2][0] = r0; b1[nh * 2][1] = r1;
                    b1[nh * 2 + 1][0] = r2; b1[nh * 2 + 1][1] = r3;
                }
            }
#pragma unroll
            for (int mi = 0; mi < 2; mi++) {
                uint32_t rel = (uint32_t)((rowA + mi * 16) << 7) + ((k0 + kadjA) << 1);
                uint32_t a00, a01, a02, a03, a10, a11, a12, a13;
                ldsm4(a00, a01, a02, a03, st + swz128(rel));
                if (full3) ldsm4(a10, a11, a12, a13, st + 16384u + swz128(rel));
#pragma unroll
                for (int nj = 0; nj < 8; nj++) {
                    mma16816(acc[mi][nj][0], acc[mi][nj][1], acc[mi][nj][2], acc[mi][nj][3],
                             a00, a01, a02, a03, b0[nj][0], b0[nj][1]);
                    if (full3) {
                        mma16816(acc[mi][nj][0], acc[mi][nj][1], acc[mi][nj][2], acc[mi][nj][3],
                                 a00, a01, a02, a03, b1[nj][0], b1[nj][1]);
                        mma16816(acc[mi][nj][0], acc[mi][nj][1], acc[mi][nj][2], acc[mi][nj][3],
                                 a10, a11, a12, a13, b0[nj][0], b0[nj][1]);
                    }
                }
            }
        }
        __syncthreads();
    }

    // epilogue: fp32 C everywhere; scaled fp16 hi comp only for Q/K blocks
    const int g = lane >> 2, tig = lane & 3;
#pragma unroll
    for (int mi = 0; mi < 2; mi++) {
        const int r0 = blockIdx.y * 128 + wm * 32 + mi * 16 + g;
#pragma unroll
        for (int nj = 0; nj < 8; nj++) {
            const int c = blockIdx.x * 256 + wn * 64 + nj * 8 + 2 * tig;
            *reinterpret_cast<float2*>(&C[(size_t)r0 * Cstride + c]) =
                make_float2(acc[mi][nj][0], acc[mi][nj][1]);
            *reinterpret_cast<float2*>(&C[(size_t)(r0 + 8) * Cstride + c]) =
                make_float2(acc[mi][nj][2], acc[mi][nj][3]);
            if (full3) {
#pragma unroll
                for (int h = 0; h < 2; h++) {
                    const int r = r0 + h * 8;
                    const size_t tbB = ((size_t)(r >> 7) * ktO + (c >> 6)) * 16384;
                    const uint32_t off = swz128(((r & 127) << 7) + ((c & 63) << 1));
                    *reinterpret_cast<uint32_t*>(reinterpret_cast<char*>(Ohi) + tbB + off) =
                        pack_h2(0.125f * acc[mi][nj][2 * h], 0.125f * acc[mi][nj][2 * h + 1]);
                }
            }
        }
    }
}

// ===========================================================================
// SCORES GEMM (r12/13, measured 97.9us): CTA 128x256, 256 threads, 8 warps
// (2m x 4n), warp m64n64, fp16 accumulation (inputs x0.125 => scores/64).
// 2-stage 96KB, 2 CTAs/SM. C(bf16) = A0@B0^T.
// ===========================================================================
__global__ __launch_bounds__(256, 2)
void score_hmma(const __half* __restrict__ A0p, const __half* __restrict__ B0p,
                __nv_bfloat16* __restrict__ Cb, int Cstride, int nch, int ktA, int ktB) {
    constexpr uint32_t STAGE_B = 3 * 16384u;

    extern __shared__ char smem[];
    const uint32_t sb = (smem_u32(smem) + 1023) & ~1023u;
    const int tid = threadIdx.x;
    const int wid = tid >> 5, lane = tid & 31;
    const int wm = wid >> 2, wn = wid & 3;  // 2m x 4n, warp m64n64

    const char* srcA0 = reinterpret_cast<const char*>(A0p) + (size_t)blockIdx.y * ktA * 16384;
    const char* srcB0a = reinterpret_cast<const char*>(B0p) + (size_t)(2 * blockIdx.x) * ktB * 16384;
    const char* srcB0b = reinterpret_cast<const char*>(B0p) + (size_t)(2 * blockIdx.x + 1) * ktB * 16384;

    auto copy_stage = [&](int s, int it) {
        const uint32_t dst = sb + (uint32_t)s * STAGE_B;
        const uint32_t lo = tid * 16;
        const size_t go = (size_t)it * 16384 + lo;
#pragma unroll
        for (int i = 0; i < 4; i++) {
            cpa16(dst + lo + i * 4096, srcA0 + go + i * 4096);
            cpa16(dst + 16384u + lo + i * 4096, srcB0a + go + i * 4096);
            cpa16(dst + 32768u + lo + i * 4096, srcB0b + go + i * 4096);
        }
    };

    copy_stage(0, 0);
    cp_commit();

    uint32_t acc[4][8][2];  // fp16x2 accumulators
#pragma unroll
    for (int a = 0; a < 4; a++)
#pragma unroll
        for (int b = 0; b < 8; b++) {
            acc[a][b][0] = 0u;
            acc[a][b][1] = 0u;
        }

    const int rowA = wm * 64 + (lane & 15);
    const int kadjA = (lane >> 4) * 8;
    const int rowBl = (wn & 1) * 64 + (lane & 7) + ((lane >> 4) << 3);
    const int kadjB = ((lane >> 3) & 1) * 8;

    for (int it = 0; it < nch; it++) {
        const int s = it & 1;
        const int nxt = it + 1;
        if (nxt < nch) copy_stage(nxt & 1, nxt);
        cp_commit();
        cp_wait<1>();
        __syncthreads();
        const uint32_t st = sb + (uint32_t)s * STAGE_B;
        const uint32_t Ab = st;
        const uint32_t Bb = st + 16384u + (uint32_t)(wn >> 1) * 16384u;
#pragma unroll
        for (int ks = 0; ks < 4; ks++) {
            const int k0 = ks * 16;
            uint32_t b[8][2];
#pragma unroll
            for (int nh = 0; nh < 4; nh++) {
                uint32_t rel = (uint32_t)((rowBl + nh * 16) << 7) + ((k0 + kadjB) << 1);
                uint32_t r0, r1, r2, r3;
                ldsm4(r0, r1, r2, r3, Bb + swz128(rel));
                b[nh * 2][0] = r0; b[nh * 2][1] = r1;
                b[nh * 2 + 1][0] = r2; b[nh * 2 + 1][1] = r3;
            }
#pragma unroll
            for (int mi = 0; mi < 4; mi++) {
                uint32_t a0, a1, a2, a3;
                uint32_t rel = (uint32_t)((rowA + mi * 16) << 7) + ((k0 + kadjA) << 1);
                ldsm4(a0, a1, a2, a3, Ab + swz128(rel));
#pragma unroll
                for (int nj = 0; nj < 8; nj++)
                    mma16816h(acc[mi][nj][0], acc[mi][nj][1], a0, a1, a2, a3,
                              b[nj][0], b[nj][1]);
            }
        }
        __syncthreads();
    }

    const int g = lane >> 2, tig = lane & 3;
#pragma unroll
    for (int mi = 0; mi < 4; mi++) {
        const int r0 = blockIdx.y * 128 + wm * 64 + mi * 16 + g;
#pragma unroll
        for (int nj = 0; nj < 8; nj++) {
            const int c = blockIdx.x * 256 + wn * 64 + nj * 8 + 2 * tig;
            const float2 f0 = __half22float2(*reinterpret_cast<__half2*>(&acc[mi][nj][0]));
            const float2 f1 = __half22float2(*reinterpret_cast<__half2*>(&acc[mi][nj][1]));
            *reinterpret_cast<uint32_t*>(&Cb[(size_t)r0 * Cstride + c]) = pack_bf2(f0.x, f0.y);
            *reinterpret_cast<uint32_t*>(&Cb[(size_t)(r0 + 8) * Cstride + c]) = pack_bf2(f1.x, f1.y);
        }
    }
}

// ===========================================================================
// Fused: candidate select on bf16 approx scores (scaled /64) + exact fp32
// re-score + softmax weights + sparse P@V gather. One block per row.
// Unscaled margin 2500 => scaled threshold 39.0625.
// ===========================================================================
__global__ __launch_bounds__(256)
void attn_refine(const __nv_bfloat16* __restrict__ St, const float* __restrict__ QKV,
                 float* __restrict__ out) {
    __shared__ float red[256];
    __shared__ int sc[256];
    __shared__ int cand[SEQ];
    __shared__ float sE[SEQ];
    __shared__ float Qs[DIM];
    const int row = blockIdx.x;
    const int tid = threadIdx.x;
    const int wid = tid >> 5, lane = tid & 31;

    const uint4* p4 = reinterpret_cast<const uint4*>(St + (size_t)row * SEQ);
    uint4 u[2];
    u[0] = p4[tid];
    u[1] = p4[tid + 256];
    float e[16];
#pragma unroll
    for (int w = 0; w < 2; w++)
#pragma unroll
        for (int j = 0; j < 4; j++) {
            const __nv_bfloat162 h = reinterpret_cast<const __nv_bfloat162*>(&u[w])[j];
            const float2 f = __bfloat1622float2(h);
            e[w * 8 + 2 * j] = f.x;
            e[w * 8 + 2 * j + 1] = f.y;
        }
    float vmax = -3.0e38f;
#pragma unroll
    for (int i = 0; i < 16; i++) vmax = fmaxf(vmax, e[i]);
    red[tid] = vmax;
    Qs[tid] = QKV[(size_t)row * NCOMB + tid];
    Qs[tid + 256] = QKV[(size_t)row * NCOMB + tid + 256];
    Qs[tid + 512] = QKV[(size_t)row * NCOMB + tid + 512];
    Qs[tid + 768] = QKV[(size_t)row * NCOMB + tid + 768];
    __syncthreads();
#pragma unroll
    for (int s = 128; s > 0; s >>= 1) {
        if (tid < s) red[tid] = fmaxf(red[tid], red[tid + s]);
        __syncthreads();
    }
    const float T = red[0] - 39.0625f;  // 2500 unscaled / 64
    __syncthreads();

    int cnt = 0;
#pragma unroll
    for (int i = 0; i < 16; i++)
        if (e[i] >= T) cnt++;
    sc[tid] = cnt;
    __syncthreads();
    for (int d = 1; d < 256; d <<= 1) {
        int val = (tid >= d) ? sc[tid - d] : 0;
        __syncthreads();
        sc[tid] += val;
        __syncthreads();
    }
    int base = sc[tid] - cnt;
    const int total = sc[255];
#pragma unroll
    for (int w = 0; w < 2; w++)
#pragma unroll
        for (int j = 0; j < 8; j++) {
            const int i = w * 8 + j;
            if (e[i] >= T) cand[base++] = w * 2048 + tid * 8 + j;
        }
    __syncthreads();

    const float4* Qs4 = reinterpret_cast<const float4*>(Qs);
    for (int c = wid; c < total; c += 8) {
        const int j = cand[c];
        const float4* Kr = reinterpret_cast<const float4*>(QKV + (size_t)j * NCOMB + DIM);
        float s = 0.0f;
#pragma unroll
        for (int t = 0; t < 8; t++) {
            const float4 kv = Kr[lane + 32 * t];
            const float4 qv = Qs4[lane + 32 * t];
            s += qv.x * kv.x + qv.y * kv.y + qv.z * kv.z + qv.w * kv.w;
        }
#pragma unroll
        for (int o = 16; o > 0; o >>= 1) s += __shfl_xor_sync(0xFFFFFFFFu, s, o);
        if (lane == 0) sE[c] = s;
    }
    __syncthreads();

    float M = -3.0e38f;
    for (int c = 0; c < total; c++) M = fmaxf(M, sE[c]);
    float sum = 0.0f;
    for (int c = 0; c < total; c++) sum += expf((sE[c] - M) * 0.03125f);
    const float inv = 1.0f / sum;

    float4 acc = make_float4(0.f, 0.f, 0.f, 0.f);
    for (int c = 0; c < total; c++) {
        const float w = expf((sE[c] - M) * 0.03125f);
        const float4 vv = *reinterpret_cast<const float4*>(
            QKV + (size_t)cand[c] * NCOMB + 2 * DIM + 4 * tid);
        acc.x += w * vv.x; acc.y += w * vv.y; acc.z += w * vv.z; acc.w += w * vv.w;
    }
    acc.x *= inv; acc.y *= inv; acc.z *= inv; acc.w *= inv;
    *reinterpret_cast<float4*>(out + (size_t)row * DIM + 4 * tid) = acc;
}

// ===========================================================================
extern "C" void kernel_launch(void* const* d_in, const int* in_sizes, int n_in,
                              void* d_out, int out_size) {
    const float* x  = (const float*)d_in[0];
    const float* wq = (const float*)d_in[1];
    const float* wk = (const float*)d_in[2];
    const float* wv = (const float*)d_in[3];
    float* out = (float*)d_out;

    float* QKV;
    __nv_bfloat16* S;
    __half *Xc, *Wc, *Hc;
    cudaGetSymbolAddress((void**)&QKV, g_QKV);
    cudaGetSymbolAddress((void**)&S, g_S);
    cudaGetSymbolAddress((void**)&Xc, g_Xc);
    cudaGetSymbolAddress((void**)&Wc, g_Wc);
    cudaGetSymbolAddress((void**)&Hc, g_Hc);
    const size_t SD = (size_t)SEQ * DIM;
    const size_t WN = (size_t)NCOMB * DIM;

    constexpr int SMEM_PROJ = 2 * 98304 + 1024;   // 2 stages x 6 tiles
    constexpr int SMEM_SCORE = 2 * 49152 + 1024;  // 2 stages x 3 tiles (2 CTAs/SM)
    cudaFuncSetAttribute(proj_hmma, cudaFuncAttributeMaxDynamicSharedMemorySize, SMEM_PROJ);
    cudaFuncSetAttribute(score_hmma, cudaFuncAttributeMaxDynamicSharedMemorySize, SMEM_SCORE);

    // splits
    split_direct2<<<512, 256>>>(x, Xc, Xc + SD);
    split_trans_w<<<dim3(128, 3), 256>>>(wq, wk, wv, Wc, Wc + WN);

    // fused QKV projection: fp32 QKV + scaled hi comps (Q/K only)
    proj_hmma<<<dim3(NCOMB / 256, SEQ / 128), 512, SMEM_PROJ>>>(
        Xc, Xc + SD, Wc, Wc + WN, QKV, Hc, NCOMB, DIM / 64, DIM / 64, DIM / 64, NCOMB / 64);

    // approx scores: S~/64 = (Qhi/8) @ (Khi/8)^T (bf16 out, fp16 accum)
    score_hmma<<<dim3(SEQ / 256, SEQ / 128), 256, SMEM_SCORE>>>(
        Hc, Hc + (size_t)16 * 8192, S, SEQ, DIM / 64, NCOMB / 64, NCOMB / 64);

    // candidate refine + softmax + sparse P@V
    attn_refine<<<SEQ, 256>>>(S, QKV, out);
}